// round 11
// baseline (speedup 1.0000x reference)
#include <cuda_runtime.h>

// MultiCellLSTM: B=4096, T=512, H=64, gates 4H=256.
// R11: k-paired f32x2 math. acc per gate = (even-k sum, odd-k sum); weights
// stored as k-pairs -> h consumed as natural float2 (NO duplication):
//   - h crossbar traffic halved (64 wf/warp-step vs 128)
//   - h stores halved, weight layout fully contiguous (swizzle eliminated)
//   - bias+input folded into EW as scalars (x LDG latency hidden by m-loop)
// 7 warps x 147 CTAs, 4 rows/warp, no barriers in main loop (converged-warp
// program order on smem, validated in R10).

typedef unsigned long long u64;

#define NTHR   224                  // 7 warps
#define NCTA   147                  // 147*7 = 1029 warps >= 1024 needed
#define NWARP  7
#define WS_U64 (3 * 32 * 256)       // 24576 u64 : k-paired weights (192KB)
#define HD_U64 (2 * NWARP * 4 * 32) // 1792  u64 : double-buffered h (14KB)
#define SMEM_BYTES ((WS_U64 + HD_U64) * 8)   // 210944

__device__ __forceinline__ float ex2f(float x) { float y; asm("ex2.approx.f32 %0, %1;" : "=f"(y) : "f"(x)); return y; }
__device__ __forceinline__ float rcpf(float x) { float y; asm("rcp.approx.f32 %0, %1;" : "=f"(y) : "f"(x)); return y; }
__device__ __forceinline__ float sigp(float x) { return rcpf(1.0f + ex2f(-1.4426950408889634f * x)); }  // final out only
__device__ __forceinline__ float tha(float x) { float y; asm("tanh.approx.f32 %0, %1;" : "=f"(y) : "f"(x)); return y; }
__device__ __forceinline__ float sga(float x) { return fmaf(0.5f, tha(0.5f * x), 0.5f); }

__device__ __forceinline__ u64 pk2(float a, float b) { u64 r; asm("mov.b64 %0, {%1, %2};" : "=l"(r) : "f"(a), "f"(b)); return r; }
__device__ __forceinline__ void up2(u64 v, float& a, float& b) { asm("mov.b64 {%0, %1}, %2;" : "=f"(a), "=f"(b) : "l"(v)); }
__device__ __forceinline__ u64 ffma2(u64 a, u64 b, u64 c) { u64 d; asm("fma.rn.f32x2 %0, %1, %2, %3;" : "=l"(d) : "l"(a), "l"(b), "l"(c)); return d; }

// Scalar per-lane bias + input-weight columns; index j = q*2+u,
// gate = q*64 + 2*lane + u (classes q: i=0,f=1,g=2,o=3; units u=0,1).
struct CmbS3 { float b[8], w1[8], w2[8], w3[8]; };
struct CmbS2 { float b[8], w1[8], w2[8]; };
struct CmbS1 { float b[8], w1[8]; };

// One LSTM step for cell type TY (0: x1+x2+x3, 1: x1+x2, 2: x1 only).
// Weight smem layout per cell (64KB): m-row m (k-pair 2m,2m+1) = 2KB at
// m*2048; within it, class q at q*512; lane l reads 16B = u64 gates
// (q*64+2l, q*64+2l+1). All warp loads are 512B contiguous -> conflict-free.
// h per row: 64 floats (256B) at hrd + r*256; ulonglong2 broadcast at j*16
// yields k-pairs (2j) and (2j+1).
template<int TY, typename CMB>
__device__ __forceinline__ void do_step(
    const char* __restrict__ wsB, const CMB& cm,
    const char* hrd,   // read h buffer (4 rows x 256B)
    char* hwr,         // write h buffer
    int lane,
    const float (&xv1)[4], const float (&xv2)[4], const float (&xv3)[4],
    float (&cst)[4][2], float (&hl)[4][2])
{
    const char* wcell = wsB + TY * 65536 + lane * 16;

    u64 a0[4][4], a1[4][4];   // [class][row], unit0 / unit1; halves = (even-k, odd-k)
    #pragma unroll
    for (int q = 0; q < 4; q++)
        #pragma unroll
        for (int r = 0; r < 4; r++) { a0[q][r] = 0ull; a1[q][r] = 0ull; }

    #pragma unroll 4
    for (int j = 0; j < 16; j++) {
        const char* b0 = wcell + j * 4096;          // m = 2j
        ulonglong2 w00 = *(const ulonglong2*)(b0);
        ulonglong2 w01 = *(const ulonglong2*)(b0 + 512);
        ulonglong2 w02 = *(const ulonglong2*)(b0 + 1024);
        ulonglong2 w03 = *(const ulonglong2*)(b0 + 1536);
        ulonglong2 w10 = *(const ulonglong2*)(b0 + 2048);   // m = 2j+1
        ulonglong2 w11 = *(const ulonglong2*)(b0 + 2560);
        ulonglong2 w12 = *(const ulonglong2*)(b0 + 3072);
        ulonglong2 w13 = *(const ulonglong2*)(b0 + 3584);
        #pragma unroll
        for (int r = 0; r < 4; r++) {
            ulonglong2 hd = *(const ulonglong2*)(hrd + r * 256 + j * 16);  // (h4j,h4j+1),(h4j+2,h4j+3)
            a0[0][r] = ffma2(w00.x, hd.x, a0[0][r]); a1[0][r] = ffma2(w00.y, hd.x, a1[0][r]);
            a0[1][r] = ffma2(w01.x, hd.x, a0[1][r]); a1[1][r] = ffma2(w01.y, hd.x, a1[1][r]);
            a0[2][r] = ffma2(w02.x, hd.x, a0[2][r]); a1[2][r] = ffma2(w02.y, hd.x, a1[2][r]);
            a0[3][r] = ffma2(w03.x, hd.x, a0[3][r]); a1[3][r] = ffma2(w03.y, hd.x, a1[3][r]);
            a0[0][r] = ffma2(w10.x, hd.y, a0[0][r]); a1[0][r] = ffma2(w10.y, hd.y, a1[0][r]);
            a0[1][r] = ffma2(w11.x, hd.y, a0[1][r]); a1[1][r] = ffma2(w11.y, hd.y, a1[1][r]);
            a0[2][r] = ffma2(w12.x, hd.y, a0[2][r]); a1[2][r] = ffma2(w12.y, hd.y, a1[2][r]);
            a0[3][r] = ffma2(w13.x, hd.y, a0[3][r]); a1[3][r] = ffma2(w13.y, hd.y, a1[3][r]);
        }
    }

    // EW: fold bias + input scalars, horizontal-add halves, LSTM cell.
    #pragma unroll
    for (int r = 0; r < 4; r++) {
        float g[4][2];
        #pragma unroll
        for (int q = 0; q < 4; q++) {
            float s0 = fmaf(cm.w1[2 * q],     xv1[r], cm.b[2 * q]);
            float s1 = fmaf(cm.w1[2 * q + 1], xv1[r], cm.b[2 * q + 1]);
            if constexpr (TY <= 1) { s0 = fmaf(cm.w2[2 * q], xv2[r], s0); s1 = fmaf(cm.w2[2 * q + 1], xv2[r], s1); }
            if constexpr (TY == 0) { s0 = fmaf(cm.w3[2 * q], xv3[r], s0); s1 = fmaf(cm.w3[2 * q + 1], xv3[r], s1); }
            float e, o;
            up2(a0[q][r], e, o); g[q][0] = (e + o) + s0;
            up2(a1[q][r], e, o); g[q][1] = (e + o) + s1;
        }
        float c0 = fmaf(sga(g[1][0]), cst[r][0], sga(g[0][0]) * tha(g[2][0]));
        float c1 = fmaf(sga(g[1][1]), cst[r][1], sga(g[0][1]) * tha(g[2][1]));
        cst[r][0] = c0; cst[r][1] = c1;
        float h0 = sga(g[3][0]) * tha(c0);
        float h1 = sga(g[3][1]) * tha(c1);
        hl[r][0] = h0; hl[r][1] = h1;
        *(u64*)(hwr + r * 256 + lane * 8) = pk2(h0, h1);   // plain (h_u0, h_u1)
    }
}

__global__ __launch_bounds__(NTHR, 1) void mclstm_kernel(
    const float* __restrict__ x1, const float* __restrict__ x2, const float* __restrict__ x3,
    const float* __restrict__ Wih3, const float* __restrict__ Whh3,
    const float* __restrict__ bih3, const float* __restrict__ bhh3,
    const float* __restrict__ Wih2, const float* __restrict__ Whh2,
    const float* __restrict__ bih2, const float* __restrict__ bhh2,
    const float* __restrict__ Wih1, const float* __restrict__ Whh1,
    const float* __restrict__ bih1, const float* __restrict__ bhh1,
    const float* __restrict__ Wout, const float* __restrict__ bOut,
    float* __restrict__ out)
{
    extern __shared__ u64 sm[];
    u64* ws   = sm;
    u64* hbuf = ws + WS_U64;   // [par][7 warps][4 rows][32 u64]

    const int tid = threadIdx.x;

    // ---- stage k-paired weights ----
    // u64 idx = ty*8192 + m*256 + q*64 + 2*l + c ; gate g = q*64 + 2l + c ;
    // value = (W[g][2m], W[g][2m+1]).
    for (int idx = tid; idx < WS_U64; idx += NTHR) {
        int ty = idx >> 13, rem = idx & 8191;
        int m = rem >> 8, r2 = rem & 255;
        int q = r2 >> 6, t = r2 & 63;
        int l = t >> 1, c = t & 1;
        int g = q * 64 + 2 * l + c;
        const float* W = (ty == 0) ? Whh3 : (ty == 1) ? Whh2 : Whh1;
        ws[idx] = pk2(W[g * 64 + 2 * m], W[g * 64 + 2 * m + 1]);
    }
    for (int idx = tid; idx < HD_U64; idx += NTHR) hbuf[idx] = 0ull;

    const int lane = tid & 31, w = tid >> 5;
    const int gw   = blockIdx.x * NWARP + w;     // global warp id
    const int row0 = gw * 4;
    const int u0 = 2 * lane, u1 = u0 + 1;

    // ---- per-lane scalar cmb: bias(+bhh) and input-weight columns ----
    CmbS3 cm3; CmbS2 cm2; CmbS1 cm1;
    #pragma unroll
    for (int q = 0; q < 4; q++) {
        #pragma unroll
        for (int u = 0; u < 2; u++) {
            int j = q * 2 + u;
            int g = q * 64 + u0 + u;
            cm3.b[j]  = bih3[g] + bhh3[g];
            cm3.w1[j] = Wih3[g * 3 + 0];
            cm3.w2[j] = Wih3[g * 3 + 1];
            cm3.w3[j] = Wih3[g * 3 + 2];
            cm2.b[j]  = bih2[g] + bhh2[g];
            cm2.w1[j] = Wih2[g * 2 + 0];
            cm2.w2[j] = Wih2[g * 2 + 1];
            cm1.b[j]  = bih1[g] + bhh1[g];
            cm1.w1[j] = Wih1[g];
        }
    }
    __syncthreads();

    if (row0 >= 4096) return;   // surplus warps (tail CTA) exit after init

    const char* wsB = (const char*)ws;
    char* hb0 = (char*)hbuf + (size_t)w * 1024;      // par 0: warp-private 1KB
    char* hb1 = hb0 + NWARP * 1024;                  // par 1

    float cst[4][2], hl[4][2];
    #pragma unroll
    for (int r = 0; r < 4; r++) { cst[r][0] = cst[r][1] = 0.f; hl[r][0] = hl[r][1] = 0.f; }

    const float* x1r = x1 + (size_t)row0 * 512;
    const float* x2r = x2 + (size_t)row0 * 256;
    const float* x3r = x3 + (size_t)row0 * 128;

    for (int b = 0; b < 128; b++) {
        float a1v[4][4], a2v[4][2], a3v[4];
        #pragma unroll
        for (int r = 0; r < 4; r++) {
            float4 v = *(const float4*)(x1r + (size_t)r * 512 + b * 4);
            a1v[r][0] = v.x; a1v[r][1] = v.y; a1v[r][2] = v.z; a1v[r][3] = v.w;
            float2 u = *(const float2*)(x2r + (size_t)r * 256 + b * 2);
            a2v[r][0] = u.x; a2v[r][1] = u.y;
            a3v[r] = x3r[(size_t)r * 128 + b];
        }
        float t1[4], t2[4];

        #pragma unroll
        for (int r = 0; r < 4; r++) { t1[r] = a1v[r][0]; t2[r] = a2v[r][0]; }
        do_step<0>(wsB, cm3, hb0, hb1, lane, t1, t2, a3v, cst, hl);  // t%4==0

        #pragma unroll
        for (int r = 0; r < 4; r++) t1[r] = a1v[r][1];
        do_step<2>(wsB, cm1, hb1, hb0, lane, t1, t1, t1, cst, hl);   // t%4==1

        #pragma unroll
        for (int r = 0; r < 4; r++) { t1[r] = a1v[r][2]; t2[r] = a2v[r][1]; }
        do_step<1>(wsB, cm2, hb0, hb1, lane, t1, t2, t2, cst, hl);   // t%4==2

        #pragma unroll
        for (int r = 0; r < 4; r++) t1[r] = a1v[r][3];
        do_step<2>(wsB, cm1, hb1, hb0, lane, t1, t1, t1, cst, hl);   // t%4==3
    }

    // out[row] = sigmoid(h . Wout + bOut): lane holds units u0,u1 per row
    const float wo0 = Wout[u0], wo1 = Wout[u1];
    const float bo = bOut[0];
    #pragma unroll
    for (int r = 0; r < 4; r++) {
        float pw = hl[r][0] * wo0 + hl[r][1] * wo1;
        pw += __shfl_xor_sync(0xffffffffu, pw, 16);
        pw += __shfl_xor_sync(0xffffffffu, pw, 8);
        pw += __shfl_xor_sync(0xffffffffu, pw, 4);
        pw += __shfl_xor_sync(0xffffffffu, pw, 2);
        pw += __shfl_xor_sync(0xffffffffu, pw, 1);
        if (lane == 0) out[row0 + r] = sigp(pw + bo);
    }
}

extern "C" void kernel_launch(void* const* d_in, const int* in_sizes, int n_in,
                              void* d_out, int out_size) {
    const float* x1   = (const float*)d_in[0];
    const float* x2   = (const float*)d_in[1];
    const float* x3   = (const float*)d_in[2];
    const float* Wih3 = (const float*)d_in[3];
    const float* Whh3 = (const float*)d_in[4];
    const float* bih3 = (const float*)d_in[5];
    const float* bhh3 = (const float*)d_in[6];
    const float* Wih2 = (const float*)d_in[7];
    const float* Whh2 = (const float*)d_in[8];
    const float* bih2 = (const float*)d_in[9];
    const float* bhh2 = (const float*)d_in[10];
    const float* Wih1 = (const float*)d_in[11];
    const float* Whh1 = (const float*)d_in[12];
    const float* bih1 = (const float*)d_in[13];
    const float* bhh1 = (const float*)d_in[14];
    const float* Wout = (const float*)d_in[15];
    const float* bOut = (const float*)d_in[16];

    cudaFuncSetAttribute(mclstm_kernel, cudaFuncAttributeMaxDynamicSharedMemorySize, SMEM_BYTES);

    mclstm_kernel<<<NCTA, NTHR, SMEM_BYTES>>>(
        x1, x2, x3,
        Wih3, Whh3, bih3, bhh3,
        Wih2, Whh2, bih2, bhh2,
        Wih1, Whh1, bih1, bhh1,
        Wout, bOut, (float*)d_out);
}

// round 12
// speedup vs baseline: 1.7263x; 1.7263x over previous
#include <cuda_runtime.h>

// MultiCellLSTM: B=4096, T=512, H=64, gates 4H=256.
// R12: R10 (7 warps x 147 CTAs, 4 rows/warp, smem weights w/ conflict-free
// swizzle, register cmb, tanh.approx, barrier-free converged-warp loop)
// with h traffic halved: h stored PLAIN (h_u0,h_u1) 8B/lane, read as 16B
// broadcasts of 4 values, duplicated to (h,h) f32x2 operands via register
// MOVs (ALU pipe has idle headroom). Accumulator layout unchanged (16 u64)
// to protect f32x2 register pairing (R11 lesson: acc doubling -> demotion).

typedef unsigned long long u64;

#define NTHR   224                  // 7 warps
#define NCTA   147                  // 147*7 = 1029 warps >= 1024 needed
#define NWARP  7
#define WS_U64 (3 * 64 * 128)       // 24576 u64 : recurrent weights (192KB)
#define HD_U64 (2 * NWARP * 4 * 32) // 1792  u64 : double-buffered plain h (14KB)
#define SMEM_BYTES ((WS_U64 + HD_U64) * 8)   // 210944

__device__ __forceinline__ float ex2f(float x) { float y; asm("ex2.approx.f32 %0, %1;" : "=f"(y) : "f"(x)); return y; }
__device__ __forceinline__ float rcpf(float x) { float y; asm("rcp.approx.f32 %0, %1;" : "=f"(y) : "f"(x)); return y; }
__device__ __forceinline__ float sigp(float x) { return rcpf(1.0f + ex2f(-1.4426950408889634f * x)); }  // final out only
__device__ __forceinline__ float tha(float x) { float y; asm("tanh.approx.f32 %0, %1;" : "=f"(y) : "f"(x)); return y; }
__device__ __forceinline__ float sga(float x) { return fmaf(0.5f, tha(0.5f * x), 0.5f); }

__device__ __forceinline__ u64 pk2(float a, float b) { u64 r; asm("mov.b64 %0, {%1, %2};" : "=l"(r) : "f"(a), "f"(b)); return r; }
__device__ __forceinline__ void up2(u64 v, float& a, float& b) { asm("mov.b64 {%0, %1}, %2;" : "=f"(a), "=f"(b) : "l"(v)); }
__device__ __forceinline__ u64 ffma2(u64 a, u64 b, u64 c) { u64 d; asm("fma.rn.f32x2 %0, %1, %2, %3;" : "=l"(d) : "l"(a), "l"(b), "l"(c)); return d; }

// Per-lane register-resident bias + input-weight columns.
// A = classes (i,f) for units (2l,2l+1); B = classes (g,o).
struct Cmb3 { ulonglong2 bA, bB, w1A, w1B, w2A, w2B, w3A, w3B; };
struct Cmb2 { ulonglong2 bA, bB, w1A, w1B, w2A, w2B; };
struct Cmb1 { ulonglong2 bA, bB, w1A, w1B; };

// One LSTM step for cell type TY (0: x1+x2+x3, 1: x1+x2, 2: x1 only).
// Lane owns units {2l,2l+1} x 4 rows. Weight k-row layout (1024B):
//   16B slot = l*32 + ((h ^ (l>>2))&1)*16; h=0 -> classes(i,f), h=1 -> (g,o).
// h row buffer: 64 floats plain (256B); lane l owns bytes l*8..l*8+7.
template<int TY, typename CMB>
__device__ __forceinline__ void do_step(
    const char* __restrict__ wsB, const CMB& cm,
    const char* hrd,   // read h buffer (4 rows x 256B)
    char* hwr,         // write h buffer
    int lane, int offA, int offB,
    const float (&xv1)[4], const float (&xv2)[4], const float (&xv3)[4],
    float (&cst)[4][2], float (&hl)[4][2])
{
    const char* wcell = wsB + TY * 65536;   // 64 k-rows * 1024B

    u64 acc[4][4];  // [class i,f,g,o][row]

    #pragma unroll
    for (int r = 0; r < 4; r++) {
        u64 xd = pk2(xv1[r], xv1[r]);
        acc[0][r] = ffma2(cm.w1A.x, xd, cm.bA.x);
        acc[1][r] = ffma2(cm.w1A.y, xd, cm.bA.y);
        acc[2][r] = ffma2(cm.w1B.x, xd, cm.bB.x);
        acc[3][r] = ffma2(cm.w1B.y, xd, cm.bB.y);
    }
    if constexpr (TY <= 1) {
        #pragma unroll
        for (int r = 0; r < 4; r++) {
            u64 xd = pk2(xv2[r], xv2[r]);
            acc[0][r] = ffma2(cm.w2A.x, xd, acc[0][r]);
            acc[1][r] = ffma2(cm.w2A.y, xd, acc[1][r]);
            acc[2][r] = ffma2(cm.w2B.x, xd, acc[2][r]);
            acc[3][r] = ffma2(cm.w2B.y, xd, acc[3][r]);
        }
    }
    if constexpr (TY == 0) {
        #pragma unroll
        for (int r = 0; r < 4; r++) {
            u64 xd = pk2(xv3[r], xv3[r]);
            acc[0][r] = ffma2(cm.w3A.x, xd, acc[0][r]);
            acc[1][r] = ffma2(cm.w3A.y, xd, acc[1][r]);
            acc[2][r] = ffma2(cm.w3B.x, xd, acc[2][r]);
            acc[3][r] = ffma2(cm.w3B.y, xd, acc[3][r]);
        }
    }

    // recurrent: j covers k = 4j..4j+3. One broadcast LDS.128 per (j,row)
    // delivers 4 h values; dup'd into f32x2 operands in registers.
    #pragma unroll 2
    for (int j = 0; j < 16; j++) {
        const char* base = wcell + j * 4096;
        ulonglong2 wA0 = *(const ulonglong2*)(base + offA);
        ulonglong2 wB0 = *(const ulonglong2*)(base + offB);
        ulonglong2 wA1 = *(const ulonglong2*)(base + 1024 + offA);
        ulonglong2 wB1 = *(const ulonglong2*)(base + 1024 + offB);
        ulonglong2 wA2 = *(const ulonglong2*)(base + 2048 + offA);
        ulonglong2 wB2 = *(const ulonglong2*)(base + 2048 + offB);
        ulonglong2 wA3 = *(const ulonglong2*)(base + 3072 + offA);
        ulonglong2 wB3 = *(const ulonglong2*)(base + 3072 + offB);
        #pragma unroll
        for (int r = 0; r < 4; r++) {
            ulonglong2 hv = *(const ulonglong2*)(hrd + r * 256 + j * 16);  // h[4j..4j+3]
            float h0, h1, h2, h3;
            up2(hv.x, h0, h1);
            up2(hv.y, h2, h3);
            u64 d0 = pk2(h0, h0), d1 = pk2(h1, h1), d2 = pk2(h2, h2), d3 = pk2(h3, h3);
            acc[0][r] = ffma2(wA0.x, d0, acc[0][r]);
            acc[1][r] = ffma2(wA0.y, d0, acc[1][r]);
            acc[2][r] = ffma2(wB0.x, d0, acc[2][r]);
            acc[3][r] = ffma2(wB0.y, d0, acc[3][r]);
            acc[0][r] = ffma2(wA1.x, d1, acc[0][r]);
            acc[1][r] = ffma2(wA1.y, d1, acc[1][r]);
            acc[2][r] = ffma2(wB1.x, d1, acc[2][r]);
            acc[3][r] = ffma2(wB1.y, d1, acc[3][r]);
            acc[0][r] = ffma2(wA2.x, d2, acc[0][r]);
            acc[1][r] = ffma2(wA2.y, d2, acc[1][r]);
            acc[2][r] = ffma2(wB2.x, d2, acc[2][r]);
            acc[3][r] = ffma2(wB2.y, d2, acc[3][r]);
            acc[0][r] = ffma2(wA3.x, d3, acc[0][r]);
            acc[1][r] = ffma2(wA3.y, d3, acc[1][r]);
            acc[2][r] = ffma2(wB3.x, d3, acc[2][r]);
            acc[3][r] = ffma2(wB3.y, d3, acc[3][r]);
        }
    }

    // elementwise LSTM cell (writes go to the other h buffer)
    #pragma unroll
    for (int r = 0; r < 4; r++) {
        float gi0, gi1, gf0, gf1, gg0, gg1, go0, go1;
        up2(acc[0][r], gi0, gi1);
        up2(acc[1][r], gf0, gf1);
        up2(acc[2][r], gg0, gg1);
        up2(acc[3][r], go0, go1);
        float c0 = fmaf(sga(gf0), cst[r][0], sga(gi0) * tha(gg0));
        float c1 = fmaf(sga(gf1), cst[r][1], sga(gi1) * tha(gg1));
        cst[r][0] = c0; cst[r][1] = c1;
        float h0 = sga(go0) * tha(c0);
        float h1 = sga(go1) * tha(c1);
        hl[r][0] = h0; hl[r][1] = h1;
        *(u64*)(hwr + r * 256 + lane * 8) = pk2(h0, h1);   // plain (h_u0, h_u1)
    }
}

__global__ __launch_bounds__(NTHR, 1) void mclstm_kernel(
    const float* __restrict__ x1, const float* __restrict__ x2, const float* __restrict__ x3,
    const float* __restrict__ Wih3, const float* __restrict__ Whh3,
    const float* __restrict__ bih3, const float* __restrict__ bhh3,
    const float* __restrict__ Wih2, const float* __restrict__ Whh2,
    const float* __restrict__ bih2, const float* __restrict__ bhh2,
    const float* __restrict__ Wih1, const float* __restrict__ Whh1,
    const float* __restrict__ bih1, const float* __restrict__ bhh1,
    const float* __restrict__ Wout, const float* __restrict__ bOut,
    float* __restrict__ out)
{
    extern __shared__ u64 sm[];
    u64* ws   = sm;
    u64* hbuf = ws + WS_U64;   // [par][7 warps][4 rows][32 u64]

    const int tid = threadIdx.x;

    // ---- stage recurrent weights: ws[(ty*64+k)*128 + slot] ----
    // slot s -> lane l=s>>2, 16B half swz=(s>>1)&1, col=s&1;
    // logical half h = swz ^ ((l>>2)&1); class q = 2h+col; units (2l,2l+1).
    for (int idx = tid; idx < WS_U64; idx += NTHR) {
        int ty = idx >> 13, rem = idx & 8191, k = rem >> 7, s = rem & 127;
        int l = s >> 2, swz = (s >> 1) & 1, col = s & 1;
        int h = swz ^ ((l >> 2) & 1);
        int q = 2 * h + col;
        const float* W = (ty == 0) ? Whh3 : (ty == 1) ? Whh2 : Whh1;
        int g0 = (q * 64 + 2 * l) * 64 + k;
        ws[idx] = pk2(W[g0], W[g0 + 64]);
    }
    for (int idx = tid; idx < HD_U64; idx += NTHR) hbuf[idx] = 0ull;

    const int lane = tid & 31, w = tid >> 5;
    const int gw   = blockIdx.x * NWARP + w;     // global warp id
    const int row0 = gw * 4;
    const int u0 = 2 * lane, u1 = u0 + 1;

    // ---- per-lane register cmb: bias(+bhh) and input-weight columns ----
    Cmb3 cm3; Cmb2 cm2; Cmb1 cm1;
    {
        // gate row = class*64 + unit; classes i=0,f=1,g=2,o=3
        #define LB(bi, bh, q) pk2(bi[(q)*64 + u0] + bh[(q)*64 + u0], bi[(q)*64 + u1] + bh[(q)*64 + u1])
        #define LW(wi, q, wic, cx) pk2(wi[((q)*64 + u0)*(wic) + (cx)], wi[((q)*64 + u1)*(wic) + (cx)])
        cm3.bA.x = LB(bih3, bhh3, 0); cm3.bA.y = LB(bih3, bhh3, 1);
        cm3.bB.x = LB(bih3, bhh3, 2); cm3.bB.y = LB(bih3, bhh3, 3);
        cm3.w1A.x = LW(Wih3, 0, 3, 0); cm3.w1A.y = LW(Wih3, 1, 3, 0);
        cm3.w1B.x = LW(Wih3, 2, 3, 0); cm3.w1B.y = LW(Wih3, 3, 3, 0);
        cm3.w2A.x = LW(Wih3, 0, 3, 1); cm3.w2A.y = LW(Wih3, 1, 3, 1);
        cm3.w2B.x = LW(Wih3, 2, 3, 1); cm3.w2B.y = LW(Wih3, 3, 3, 1);
        cm3.w3A.x = LW(Wih3, 0, 3, 2); cm3.w3A.y = LW(Wih3, 1, 3, 2);
        cm3.w3B.x = LW(Wih3, 2, 3, 2); cm3.w3B.y = LW(Wih3, 3, 3, 2);

        cm2.bA.x = LB(bih2, bhh2, 0); cm2.bA.y = LB(bih2, bhh2, 1);
        cm2.bB.x = LB(bih2, bhh2, 2); cm2.bB.y = LB(bih2, bhh2, 3);
        cm2.w1A.x = LW(Wih2, 0, 2, 0); cm2.w1A.y = LW(Wih2, 1, 2, 0);
        cm2.w1B.x = LW(Wih2, 2, 2, 0); cm2.w1B.y = LW(Wih2, 3, 2, 0);
        cm2.w2A.x = LW(Wih2, 0, 2, 1); cm2.w2A.y = LW(Wih2, 1, 2, 1);
        cm2.w2B.x = LW(Wih2, 2, 2, 1); cm2.w2B.y = LW(Wih2, 3, 2, 1);

        cm1.bA.x = LB(bih1, bhh1, 0); cm1.bA.y = LB(bih1, bhh1, 1);
        cm1.bB.x = LB(bih1, bhh1, 2); cm1.bB.y = LB(bih1, bhh1, 3);
        cm1.w1A.x = LW(Wih1, 0, 1, 0); cm1.w1A.y = LW(Wih1, 1, 1, 0);
        cm1.w1B.x = LW(Wih1, 2, 1, 0); cm1.w1B.y = LW(Wih1, 3, 1, 0);
        #undef LB
        #undef LW
    }
    __syncthreads();

    if (row0 >= 4096) return;   // surplus warps (tail CTA) exit after init

    const int s0   = ((lane >> 2) & 1) * 16;
    const int offA = lane * 32 + s0;        // classes (i,f)
    const int offB = lane * 32 + 16 - s0;   // classes (g,o)

    const char* wsB = (const char*)ws;
    char* hb0 = (char*)hbuf + (size_t)w * 1024;      // par 0: warp-private 1KB
    char* hb1 = hb0 + NWARP * 1024;                  // par 1

    float cst[4][2], hl[4][2];
    #pragma unroll
    for (int r = 0; r < 4; r++) { cst[r][0] = cst[r][1] = 0.f; hl[r][0] = hl[r][1] = 0.f; }

    const float* x1r = x1 + (size_t)row0 * 512;
    const float* x2r = x2 + (size_t)row0 * 256;
    const float* x3r = x3 + (size_t)row0 * 128;

    for (int b = 0; b < 128; b++) {
        float a1v[4][4], a2v[4][2], a3v[4];
        #pragma unroll
        for (int r = 0; r < 4; r++) {
            float4 v = *(const float4*)(x1r + (size_t)r * 512 + b * 4);
            a1v[r][0] = v.x; a1v[r][1] = v.y; a1v[r][2] = v.z; a1v[r][3] = v.w;
            float2 u = *(const float2*)(x2r + (size_t)r * 256 + b * 2);
            a2v[r][0] = u.x; a2v[r][1] = u.y;
            a3v[r] = x3r[(size_t)r * 128 + b];
        }
        float t1[4], t2[4];

        #pragma unroll
        for (int r = 0; r < 4; r++) { t1[r] = a1v[r][0]; t2[r] = a2v[r][0]; }
        do_step<0>(wsB, cm3, hb0, hb1, lane, offA, offB, t1, t2, a3v, cst, hl);  // t%4==0

        #pragma unroll
        for (int r = 0; r < 4; r++) t1[r] = a1v[r][1];
        do_step<2>(wsB, cm1, hb1, hb0, lane, offA, offB, t1, t1, t1, cst, hl);   // t%4==1

        #pragma unroll
        for (int r = 0; r < 4; r++) { t1[r] = a1v[r][2]; t2[r] = a2v[r][1]; }
        do_step<1>(wsB, cm2, hb0, hb1, lane, offA, offB, t1, t2, t2, cst, hl);   // t%4==2

        #pragma unroll
        for (int r = 0; r < 4; r++) t1[r] = a1v[r][3];
        do_step<2>(wsB, cm1, hb1, hb0, lane, offA, offB, t1, t1, t1, cst, hl);   // t%4==3
    }

    // out[row] = sigmoid(h . Wout + bOut): lane holds 2 units per row
    const float wo0 = Wout[u0], wo1 = Wout[u1];
    const float bo = bOut[0];
    #pragma unroll
    for (int r = 0; r < 4; r++) {
        float pw = hl[r][0] * wo0 + hl[r][1] * wo1;
        pw += __shfl_xor_sync(0xffffffffu, pw, 16);
        pw += __shfl_xor_sync(0xffffffffu, pw, 8);
        pw += __shfl_xor_sync(0xffffffffu, pw, 4);
        pw += __shfl_xor_sync(0xffffffffu, pw, 2);
        pw += __shfl_xor_sync(0xffffffffu, pw, 1);
        if (lane == 0) out[row0 + r] = sigp(pw + bo);
    }
}

extern "C" void kernel_launch(void* const* d_in, const int* in_sizes, int n_in,
                              void* d_out, int out_size) {
    const float* x1   = (const float*)d_in[0];
    const float* x2   = (const float*)d_in[1];
    const float* x3   = (const float*)d_in[2];
    const float* Wih3 = (const float*)d_in[3];
    const float* Whh3 = (const float*)d_in[4];
    const float* bih3 = (const float*)d_in[5];
    const float* bhh3 = (const float*)d_in[6];
    const float* Wih2 = (const float*)d_in[7];
    const float* Whh2 = (const float*)d_in[8];
    const float* bih2 = (const float*)d_in[9];
    const float* bhh2 = (const float*)d_in[10];
    const float* Wih1 = (const float*)d_in[11];
    const float* Whh1 = (const float*)d_in[12];
    const float* bih1 = (const float*)d_in[13];
    const float* bhh1 = (const float*)d_in[14];
    const float* Wout = (const float*)d_in[15];
    const float* bOut = (const float*)d_in[16];

    cudaFuncSetAttribute(mclstm_kernel, cudaFuncAttributeMaxDynamicSharedMemorySize, SMEM_BYTES);

    mclstm_kernel<<<NCTA, NTHR, SMEM_BYTES>>>(
        x1, x2, x3,
        Wih3, Whh3, bih3, bhh3,
        Wih2, Whh2, bih2, bhh2,
        Wih1, Whh1, bih1, bhh1,
        Wout, bOut, (float*)d_out);
}

// round 13
// speedup vs baseline: 1.8328x; 1.0617x over previous
#include <cuda_runtime.h>

// MultiCellLSTM: B=4096, T=512, H=64, gates 4H=256.
// R13: R12 (7 warps x 147 CTAs, 4 rows/warp, smem weights, plain-h + reg-dup,
// barrier-free converged-warp loop) plus stall surgery:
//  - acc zero-init; bias + input terms folded into EW as scalars -> m-loop
//    chains start immediately; x LDG latency hidden behind the recurrence
//  - classes i,f,o pre-scaled by 0.5 (exact) -> sigmoid = 0.5*tanh(acc)+0.5,
//    removing the inner 0.5x multiply from 3 of 5 MUFU chains per unit
//  - j-loop unroll 4, loads hoisted per body

typedef unsigned long long u64;

#define NTHR   224                  // 7 warps
#define NCTA   147                  // 147*7 = 1029 warps >= 1024 needed
#define NWARP  7
#define WS_U64 (3 * 64 * 128)       // 24576 u64 : recurrent weights (192KB)
#define HD_U64 (2 * NWARP * 4 * 32) // 1792  u64 : double-buffered plain h (14KB)
#define SMEM_BYTES ((WS_U64 + HD_U64) * 8)   // 210944

__device__ __forceinline__ float ex2f(float x) { float y; asm("ex2.approx.f32 %0, %1;" : "=f"(y) : "f"(x)); return y; }
__device__ __forceinline__ float rcpf(float x) { float y; asm("rcp.approx.f32 %0, %1;" : "=f"(y) : "f"(x)); return y; }
__device__ __forceinline__ float sigp(float x) { return rcpf(1.0f + ex2f(-1.4426950408889634f * x)); }  // final out only
__device__ __forceinline__ float tha(float x) { float y; asm("tanh.approx.f32 %0, %1;" : "=f"(y) : "f"(x)); return y; }

__device__ __forceinline__ u64 pk2(float a, float b) { u64 r; asm("mov.b64 %0, {%1, %2};" : "=l"(r) : "f"(a), "f"(b)); return r; }
__device__ __forceinline__ void up2(u64 v, float& a, float& b) { asm("mov.b64 {%0, %1}, %2;" : "=f"(a), "=f"(b) : "l"(v)); }
__device__ __forceinline__ u64 ffma2(u64 a, u64 b, u64 c) { u64 d; asm("fma.rn.f32x2 %0, %1, %2, %3;" : "=l"(d) : "l"(a), "l"(b), "l"(c)); return d; }

// Scalar per-lane bias + input-weight columns; index j = q*2+u,
// gate = q*64 + 2*lane + u. Classes i(0),f(1),o(3) pre-scaled by 0.5.
struct CmbS3 { float b[8], w1[8], w2[8], w3[8]; };
struct CmbS2 { float b[8], w1[8], w2[8]; };
struct CmbS1 { float b[8], w1[8]; };

// One LSTM step for cell type TY (0: x1+x2+x3, 1: x1+x2, 2: x1 only).
// Lane owns units {2l,2l+1} x 4 rows. Weight k-row layout (1024B):
//   16B slot = l*32 + ((h ^ (l>>2))&1)*16; h=0 -> classes(i,f), h=1 -> (g,o).
// h row buffer: 64 floats plain (256B); lane l owns bytes l*8..l*8+7.
template<int TY, typename CMB>
__device__ __forceinline__ void do_step(
    const char* __restrict__ wsB, const CMB& cm,
    const char* hrd,   // read h buffer (4 rows x 256B)
    char* hwr,         // write h buffer
    int lane, int offA, int offB,
    const float (&xv1)[4], const float (&xv2)[4], const float (&xv3)[4],
    float (&cst)[4][2], float (&hl)[4][2])
{
    const char* wcell = wsB + TY * 65536;   // 64 k-rows * 1024B

    u64 acc[4][4];  // [class i,f,g,o][row] -- zero-init: chains start free
    #pragma unroll
    for (int q = 0; q < 4; q++)
        #pragma unroll
        for (int r = 0; r < 4; r++) acc[q][r] = 0ull;

    // recurrent: j covers k = 4j..4j+3. One broadcast LDS.128 per (j,row)
    // delivers 4 h values; dup'd into f32x2 operands in registers.
    #pragma unroll 4
    for (int j = 0; j < 16; j++) {
        const char* base = wcell + j * 4096;
        ulonglong2 wA0 = *(const ulonglong2*)(base + offA);
        ulonglong2 wB0 = *(const ulonglong2*)(base + offB);
        ulonglong2 wA1 = *(const ulonglong2*)(base + 1024 + offA);
        ulonglong2 wB1 = *(const ulonglong2*)(base + 1024 + offB);
        ulonglong2 wA2 = *(const ulonglong2*)(base + 2048 + offA);
        ulonglong2 wB2 = *(const ulonglong2*)(base + 2048 + offB);
        ulonglong2 wA3 = *(const ulonglong2*)(base + 3072 + offA);
        ulonglong2 wB3 = *(const ulonglong2*)(base + 3072 + offB);
        ulonglong2 hv0 = *(const ulonglong2*)(hrd + 0 * 256 + j * 16);
        ulonglong2 hv1 = *(const ulonglong2*)(hrd + 1 * 256 + j * 16);
        ulonglong2 hv2 = *(const ulonglong2*)(hrd + 2 * 256 + j * 16);
        ulonglong2 hv3 = *(const ulonglong2*)(hrd + 3 * 256 + j * 16);
        ulonglong2 hvv[4] = {hv0, hv1, hv2, hv3};
        #pragma unroll
        for (int r = 0; r < 4; r++) {
            float h0, h1, h2, h3;
            up2(hvv[r].x, h0, h1);
            up2(hvv[r].y, h2, h3);
            u64 d0 = pk2(h0, h0), d1 = pk2(h1, h1), d2 = pk2(h2, h2), d3 = pk2(h3, h3);
            acc[0][r] = ffma2(wA0.x, d0, acc[0][r]);
            acc[1][r] = ffma2(wA0.y, d0, acc[1][r]);
            acc[2][r] = ffma2(wB0.x, d0, acc[2][r]);
            acc[3][r] = ffma2(wB0.y, d0, acc[3][r]);
            acc[0][r] = ffma2(wA1.x, d1, acc[0][r]);
            acc[1][r] = ffma2(wA1.y, d1, acc[1][r]);
            acc[2][r] = ffma2(wB1.x, d1, acc[2][r]);
            acc[3][r] = ffma2(wB1.y, d1, acc[3][r]);
            acc[0][r] = ffma2(wA2.x, d2, acc[0][r]);
            acc[1][r] = ffma2(wA2.y, d2, acc[1][r]);
            acc[2][r] = ffma2(wB2.x, d2, acc[2][r]);
            acc[3][r] = ffma2(wB2.y, d2, acc[3][r]);
            acc[0][r] = ffma2(wA3.x, d3, acc[0][r]);
            acc[1][r] = ffma2(wA3.y, d3, acc[1][r]);
            acc[2][r] = ffma2(wB3.x, d3, acc[2][r]);
            acc[3][r] = ffma2(wB3.y, d3, acc[3][r]);
        }
    }

    // EW: fold bias + input scalars (pre-scaled for i,f,o), LSTM cell.
    #pragma unroll
    for (int r = 0; r < 4; r++) {
        float g[4][2];
        #pragma unroll
        for (int q = 0; q < 4; q++) {
            float p0 = fmaf(cm.w1[2 * q],     xv1[r], cm.b[2 * q]);
            float p1 = fmaf(cm.w1[2 * q + 1], xv1[r], cm.b[2 * q + 1]);
            if constexpr (TY <= 1) { p0 = fmaf(cm.w2[2 * q], xv2[r], p0); p1 = fmaf(cm.w2[2 * q + 1], xv2[r], p1); }
            if constexpr (TY == 0) { p0 = fmaf(cm.w3[2 * q], xv3[r], p0); p1 = fmaf(cm.w3[2 * q + 1], xv3[r], p1); }
            float s0, s1;
            up2(acc[q][r], s0, s1);
            g[q][0] = s0 + p0;
            g[q][1] = s1 + p1;
        }
        // classes i,f,o hold 0.5*gate -> sigmoid = 0.5*tanh(acc)+0.5
        float si0 = fmaf(0.5f, tha(g[0][0]), 0.5f);
        float si1 = fmaf(0.5f, tha(g[0][1]), 0.5f);
        float sf0 = fmaf(0.5f, tha(g[1][0]), 0.5f);
        float sf1 = fmaf(0.5f, tha(g[1][1]), 0.5f);
        float so0 = fmaf(0.5f, tha(g[3][0]), 0.5f);
        float so1 = fmaf(0.5f, tha(g[3][1]), 0.5f);
        float tg0 = tha(g[2][0]);
        float tg1 = tha(g[2][1]);
        float c0 = fmaf(sf0, cst[r][0], si0 * tg0);
        float c1 = fmaf(sf1, cst[r][1], si1 * tg1);
        cst[r][0] = c0; cst[r][1] = c1;
        float h0 = so0 * tha(c0);
        float h1 = so1 * tha(c1);
        hl[r][0] = h0; hl[r][1] = h1;
        *(u64*)(hwr + r * 256 + lane * 8) = pk2(h0, h1);   // plain (h_u0, h_u1)
    }
}

__global__ __launch_bounds__(NTHR, 1) void mclstm_kernel(
    const float* __restrict__ x1, const float* __restrict__ x2, const float* __restrict__ x3,
    const float* __restrict__ Wih3, const float* __restrict__ Whh3,
    const float* __restrict__ bih3, const float* __restrict__ bhh3,
    const float* __restrict__ Wih2, const float* __restrict__ Whh2,
    const float* __restrict__ bih2, const float* __restrict__ bhh2,
    const float* __restrict__ Wih1, const float* __restrict__ Whh1,
    const float* __restrict__ bih1, const float* __restrict__ bhh1,
    const float* __restrict__ Wout, const float* __restrict__ bOut,
    float* __restrict__ out)
{
    extern __shared__ u64 sm[];
    u64* ws   = sm;
    u64* hbuf = ws + WS_U64;   // [par][7 warps][4 rows][32 u64]

    const int tid = threadIdx.x;

    // ---- stage recurrent weights: ws[(ty*64+k)*128 + slot] ----
    // slot s -> lane l=s>>2, 16B half swz=(s>>1)&1, col=s&1;
    // logical half h = swz ^ ((l>>2)&1); class q = 2h+col; units (2l,2l+1).
    // Classes i(0), f(1), o(3) scaled by 0.5 (exact).
    for (int idx = tid; idx < WS_U64; idx += NTHR) {
        int ty = idx >> 13, rem = idx & 8191, k = rem >> 7, s = rem & 127;
        int l = s >> 2, swz = (s >> 1) & 1, col = s & 1;
        int h = swz ^ ((l >> 2) & 1);
        int q = 2 * h + col;
        const float* W = (ty == 0) ? Whh3 : (ty == 1) ? Whh2 : Whh1;
        int g0 = (q * 64 + 2 * l) * 64 + k;
        float sc = (q == 2) ? 1.0f : 0.5f;
        ws[idx] = pk2(W[g0] * sc, W[g0 + 64] * sc);
    }
    for (int idx = tid; idx < HD_U64; idx += NTHR) hbuf[idx] = 0ull;

    const int lane = tid & 31, w = tid >> 5;
    const int gw   = blockIdx.x * NWARP + w;     // global warp id
    const int row0 = gw * 4;
    const int u0 = 2 * lane;

    // ---- per-lane scalar cmb (bias+bhh, input-weight cols), 0.5-scaled for i,f,o ----
    CmbS3 cm3; CmbS2 cm2; CmbS1 cm1;
    #pragma unroll
    for (int q = 0; q < 4; q++) {
        float sc = (q == 2) ? 1.0f : 0.5f;
        #pragma unroll
        for (int u = 0; u < 2; u++) {
            int j = q * 2 + u;
            int g = q * 64 + u0 + u;
            cm3.b[j]  = (bih3[g] + bhh3[g]) * sc;
            cm3.w1[j] = Wih3[g * 3 + 0] * sc;
            cm3.w2[j] = Wih3[g * 3 + 1] * sc;
            cm3.w3[j] = Wih3[g * 3 + 2] * sc;
            cm2.b[j]  = (bih2[g] + bhh2[g]) * sc;
            cm2.w1[j] = Wih2[g * 2 + 0] * sc;
            cm2.w2[j] = Wih2[g * 2 + 1] * sc;
            cm1.b[j]  = (bih1[g] + bhh1[g]) * sc;
            cm1.w1[j] = Wih1[g] * sc;
        }
    }
    __syncthreads();

    if (row0 >= 4096) return;   // surplus warps (tail CTA) exit after init

    const int s0   = ((lane >> 2) & 1) * 16;
    const int offA = lane * 32 + s0;        // classes (i,f)
    const int offB = lane * 32 + 16 - s0;   // classes (g,o)

    const char* wsB = (const char*)ws;
    char* hb0 = (char*)hbuf + (size_t)w * 1024;      // par 0: warp-private 1KB
    char* hb1 = hb0 + NWARP * 1024;                  // par 1

    float cst[4][2], hl[4][2];
    #pragma unroll
    for (int r = 0; r < 4; r++) { cst[r][0] = cst[r][1] = 0.f; hl[r][0] = hl[r][1] = 0.f; }

    const float* x1r = x1 + (size_t)row0 * 512;
    const float* x2r = x2 + (size_t)row0 * 256;
    const float* x3r = x3 + (size_t)row0 * 128;

    for (int b = 0; b < 128; b++) {
        float a1v[4][4], a2v[4][2], a3v[4];
        #pragma unroll
        for (int r = 0; r < 4; r++) {
            float4 v = *(const float4*)(x1r + (size_t)r * 512 + b * 4);
            a1v[r][0] = v.x; a1v[r][1] = v.y; a1v[r][2] = v.z; a1v[r][3] = v.w;
            float2 u = *(const float2*)(x2r + (size_t)r * 256 + b * 2);
            a2v[r][0] = u.x; a2v[r][1] = u.y;
            a3v[r] = x3r[(size_t)r * 128 + b];
        }
        float t1[4], t2[4];

        // x consumed only in the EW phase -> LDG latency hidden by m-loop
        #pragma unroll
        for (int r = 0; r < 4; r++) { t1[r] = a1v[r][0]; t2[r] = a2v[r][0]; }
        do_step<0>(wsB, cm3, hb0, hb1, lane, offA, offB, t1, t2, a3v, cst, hl);  // t%4==0

        #pragma unroll
        for (int r = 0; r < 4; r++) t1[r] = a1v[r][1];
        do_step<2>(wsB, cm1, hb1, hb0, lane, offA, offB, t1, t1, t1, cst, hl);   // t%4==1

        #pragma unroll
        for (int r = 0; r < 4; r++) { t1[r] = a1v[r][2]; t2[r] = a2v[r][1]; }
        do_step<1>(wsB, cm2, hb0, hb1, lane, offA, offB, t1, t2, t2, cst, hl);   // t%4==2

        #pragma unroll
        for (int r = 0; r < 4; r++) t1[r] = a1v[r][3];
        do_step<2>(wsB, cm1, hb1, hb0, lane, offA, offB, t1, t1, t1, cst, hl);   // t%4==3
    }

    // out[row] = sigmoid(h . Wout + bOut): lane holds 2 units per row
    const float wo0 = Wout[u0], wo1 = Wout[u0 + 1];
    const float bo = bOut[0];
    #pragma unroll
    for (int r = 0; r < 4; r++) {
        float pw = hl[r][0] * wo0 + hl[r][1] * wo1;
        pw += __shfl_xor_sync(0xffffffffu, pw, 16);
        pw += __shfl_xor_sync(0xffffffffu, pw, 8);
        pw += __shfl_xor_sync(0xffffffffu, pw, 4);
        pw += __shfl_xor_sync(0xffffffffu, pw, 2);
        pw += __shfl_xor_sync(0xffffffffu, pw, 1);
        if (lane == 0) out[row0 + r] = sigp(pw + bo);
    }
}

extern "C" void kernel_launch(void* const* d_in, const int* in_sizes, int n_in,
                              void* d_out, int out_size) {
    const float* x1   = (const float*)d_in[0];
    const float* x2   = (const float*)d_in[1];
    const float* x3   = (const float*)d_in[2];
    const float* Wih3 = (const float*)d_in[3];
    const float* Whh3 = (const float*)d_in[4];
    const float* bih3 = (const float*)d_in[5];
    const float* bhh3 = (const float*)d_in[6];
    const float* Wih2 = (const float*)d_in[7];
    const float* Whh2 = (const float*)d_in[8];
    const float* bih2 = (const float*)d_in[9];
    const float* bhh2 = (const float*)d_in[10];
    const float* Wih1 = (const float*)d_in[11];
    const float* Whh1 = (const float*)d_in[12];
    const float* bih1 = (const float*)d_in[13];
    const float* bhh1 = (const float*)d_in[14];
    const float* Wout = (const float*)d_in[15];
    const float* bOut = (const float*)d_in[16];

    cudaFuncSetAttribute(mclstm_kernel, cudaFuncAttributeMaxDynamicSharedMemorySize, SMEM_BYTES);

    mclstm_kernel<<<NCTA, NTHR, SMEM_BYTES>>>(
        x1, x2, x3,
        Wih3, Whh3, bih3, bhh3,
        Wih2, Whh2, bih2, bhh2,
        Wih1, Whh1, bih1, bhh1,
        Wout, bOut, (float*)d_out);
}